// round 1
// baseline (speedup 1.0000x reference)
#include <cuda_runtime.h>

// Scratch: v[b][i] = sum_j W[i][j] * context[b][j], B=8, H=1024
__device__ float g_v[8 * 1024];

#define H 1024
#define B 8
#define T 4096

// Kernel 1: one warp per W row i; each warp keeps 8 accumulators (one per batch)
// so W (4 MiB) is streamed exactly once.
__global__ void __launch_bounds__(256) compute_v_kernel(
    const float* __restrict__ W,     // (H, H)
    const float* __restrict__ ctx)   // (B, H)
{
    const int warp = threadIdx.x >> 5;
    const int lane = threadIdx.x & 31;
    const int i = blockIdx.x * 8 + warp;      // W row, grid = 128 blocks * 8 warps = 1024

    const float4* wr = reinterpret_cast<const float4*>(W + (size_t)i * H);
    float acc[B];
#pragma unroll
    for (int b = 0; b < B; b++) acc[b] = 0.0f;

#pragma unroll
    for (int k = 0; k < (H / 4) / 32; k++) {   // 8 iterations
        const int idx = lane + 32 * k;
        const float4 w4 = wr[idx];
#pragma unroll
        for (int b = 0; b < B; b++) {
            const float4 c4 = reinterpret_cast<const float4*>(ctx + b * H)[idx];
            acc[b] += w4.x * c4.x + w4.y * c4.y + w4.z * c4.z + w4.w * c4.w;
        }
    }

#pragma unroll
    for (int b = 0; b < B; b++) {
        float s = acc[b];
#pragma unroll
        for (int o = 16; o; o >>= 1) s += __shfl_xor_sync(0xFFFFFFFFu, s, o);
        if (lane == 0) g_v[b * H + i] = s;
    }
}

// Kernel 2: one warp per (b,t) row. 8 warps/block => block covers 8 consecutive
// rows, all in the same batch (4096 rows per batch, 512 blocks per batch).
// v[b] is staged in shared memory (4 KB).
__global__ void __launch_bounds__(256) score_kernel(
    const float* __restrict__ states,  // (B, T, H)
    const float* __restrict__ bias,    // (1,)
    float* __restrict__ out)           // (B*T,)
{
    __shared__ float sv[H];

    const int b = blockIdx.x >> 9;     // blockIdx.x / 512
    for (int idx = threadIdx.x; idx < H; idx += 256)
        sv[idx] = g_v[b * H + idx];
    __syncthreads();

    const int row  = blockIdx.x * 8 + (threadIdx.x >> 5);  // global (b*T + t)
    const int lane = threadIdx.x & 31;

    const float4* s4 = reinterpret_cast<const float4*>(states + (size_t)row * H);
    const float4* v4 = reinterpret_cast<const float4*>(sv);

    float acc = 0.0f;
#pragma unroll
    for (int k = 0; k < 8; k++) {
        const int idx = lane + 32 * k;
        const float4 x = s4[idx];
        const float4 w = v4[idx];
        acc += x.x * w.x + x.y * w.y + x.z * w.z + x.w * w.w;
    }

#pragma unroll
    for (int o = 16; o; o >>= 1) acc += __shfl_xor_sync(0xFFFFFFFFu, acc, o);

    if (lane == 0) out[row] = acc + bias[0];
}

extern "C" void kernel_launch(void* const* d_in, const int* in_sizes, int n_in,
                              void* d_out, int out_size)
{
    const float* states = (const float*)d_in[0];   // (B, T, H)
    const float* ctx    = (const float*)d_in[1];   // (B, H)
    const float* W      = (const float*)d_in[2];   // (1, H, H)
    const float* bias   = (const float*)d_in[3];   // (1,)
    float* out = (float*)d_out;                    // (B, T, 1)

    compute_v_kernel<<<H / 8, 256>>>(W, ctx);
    score_kernel<<<(B * T) / 8, 256>>>(states, bias, out);
}